// round 12
// baseline (speedup 1.0000x reference)
#include <cuda_runtime.h>
#include <cuda_bf16.h>
#include <cstdint>

static constexpr int B = 16, H = 256, W = 256;
static constexpr int CIN0 = 3, CMID = 16, COUT = 64;
static constexpr float BN_EPS = 1e-5f;

// h1/h2 stored pre-split NCHW: (bf16_hi << 16) | bf16_lo per element
__device__ uint32_t g_h1[(size_t)B * CMID * H * W];
__device__ uint32_t g_h2[(size_t)B * CMID * H * W];
__device__ float g_stats[2 * COUT];
__device__ float g_scale[COUT];
__device__ float g_shift[COUT];

// ---- helpers ---------------------------------------------------------------
__device__ __forceinline__ uint32_t smem_u32(const void* p) {
    uint32_t a;
    asm("{ .reg .u64 t; cvta.to.shared.u64 t, %1; cvt.u32.u64 %0, t; }"
        : "=r"(a) : "l"(p));
    return a;
}
__device__ __forceinline__ void sts64(uint32_t a, uint32_t x, uint32_t y) {
    asm volatile("st.shared.v2.u32 [%0], {%1,%2};" :: "r"(a), "r"(x), "r"(y));
}
__device__ __forceinline__ void sts16(uint32_t a, uint16_t v) {
    asm volatile("st.shared.u16 [%0], %1;" :: "r"(a), "h"(v));
}
__device__ __forceinline__ uint32_t lds32(uint32_t a) {
    uint32_t v;
    asm volatile("ld.shared.b32 %0, [%1];" : "=r"(v) : "r"(a));
    return v;
}
__device__ __forceinline__ uint32_t packhl(float v) {
    __nv_bfloat16 h = __float2bfloat16_rn(v);
    float lo = v - __bfloat162float(h);
    __nv_bfloat16 l = __float2bfloat16_rn(lo);
    return ((uint32_t)__bfloat16_as_ushort(h) << 16) |
           (uint32_t)__bfloat16_as_ushort(l);
}
__device__ __forceinline__ void mma_bf16(float d[4], const uint32_t a[4],
                                         const uint32_t b[2]) {
    asm volatile(
        "mma.sync.aligned.m16n8k16.row.col.f32.bf16.bf16.f32 "
        "{%0,%1,%2,%3},{%4,%5,%6,%7},{%8,%9},{%0,%1,%2,%3};"
        : "+f"(d[0]), "+f"(d[1]), "+f"(d[2]), "+f"(d[3])
        : "r"(a[0]), "r"(a[1]), "r"(a[2]), "r"(a[3]), "r"(b[0]), "r"(b[1]));
}

// ---- tensor-core 3x3 conv (16 in-ch), split-bf16 3-term --------------------
// Tile: 32 px (M) x CO. A per input row: [32 px][K=48], stride 112 B, hi+lo;
// RING OF 6 rows. B per dy: [CO][48], hi+lo. Two output rows per barrier;
// B fragments reused across the two rows via a Bprev/Bcur register pair.
static constexpr int ALO   = 3584;              // lo half offset within slot
static constexpr int ASLOT = 7168;              // hi + lo per row
static constexpr int BBASE = 6 * ASLOT;         // 43008
static constexpr int NY    = 8;
static constexpr int NITER = NY / 2;

template <int NTT>
__device__ __forceinline__ void stage_load_row(const uint32_t* in, int b,
                                               int yin, int x0, int tid,
                                               uint32_t v[2][4]) {
    constexpr int NSUB = (136 + NTT - 1) / NTT;
    #pragma unroll
    for (int j = 0; j < NSUB; ++j) {
        v[j][0] = v[j][1] = v[j][2] = v[j][3] = 0;
        const int it = tid + j * NTT;
        if (it >= 136) continue;
        const int cig = it / 34, xl = it - cig * 34, xin = x0 - 1 + xl;
        if (xin >= 0 && xin < W) {
            const uint32_t* p =
                in + (((size_t)b * CMID + cig * 4) * H + yin) * W + xin;
            const size_t st = (size_t)H * W;
            v[j][0] = p[0]; v[j][1] = p[st];
            v[j][2] = p[2 * st]; v[j][3] = p[3 * st];
        }
    }
}
template <int NTT>
__device__ __forceinline__ void stage_store_row(uint32_t s32, int yin, int tid,
                                                const uint32_t v[2][4]) {
    const uint32_t Ah = s32 + (uint32_t)(yin % 6) * ASLOT;
    constexpr int NSUB = (136 + NTT - 1) / NTT;
    #pragma unroll
    for (int j = 0; j < NSUB; ++j) {
        const int it = tid + j * NTT;
        if (it >= 136) continue;
        const int cig = it / 34, xl = it - cig * 34;
        const uint32_t h0 = __byte_perm(v[j][0], v[j][1], 0x7632);
        const uint32_t h1 = __byte_perm(v[j][2], v[j][3], 0x7632);
        const uint32_t l0 = __byte_perm(v[j][0], v[j][1], 0x5410);
        const uint32_t l1 = __byte_perm(v[j][2], v[j][3], 0x5410);
        #pragma unroll
        for (int dx = 0; dx < 3; ++dx) {
            const int r = xl - dx;
            if (r < 0 || r >= 32) continue;
            const uint32_t off = (uint32_t)(r * 112 + (dx * 16 + cig * 4) * 2);
            sts64(Ah + off, h0, h1);
            sts64(Ah + ALO + off, l0, l1);
        }
    }
}

// Warp grid 2 x WN (MF=1, M=32). WN*NF*8 == CO. NTT = 2*WN*32 threads.
template <int CO, int WN, int NF, bool STATS, bool OUTF32>
__global__ void __launch_bounds__(2 * WN * 32, (2 * WN * 32 == 256) ? 2 : 4)
conv_mma(const uint32_t* __restrict__ in, const float* __restrict__ wgt,
         void* __restrict__ outv) {
    constexpr int NTT  = 2 * WN * 32;
    static_assert(WN * NF * 8 == CO, "");
    constexpr int BLO  = CO * 112;
    constexpr int BDY  = 2 * BLO;
    constexpr int SOFF = BBASE + 3 * BDY;

    extern __shared__ char sm[];
    const uint32_t s32 = smem_u32(sm);
    float* sstats = (float*)(sm + SOFF);
    const int tid = threadIdx.x, wid = tid >> 5, lid = tid & 31;
    const int g = lid >> 2, tig = lid & 3;
    int bid = blockIdx.x;
    const int xs = bid & 7, ys = (bid >> 3) & 31, b = bid >> 8;
    const int x0 = xs * 32, y0 = ys * NY;

    if (STATS && tid < 128) sstats[tid] = 0.f;
    for (int i = tid; i < CO * CMID * 9; i += NTT) {      // weights -> B tiles
        const int dx = i % 3; int t = i / 3;
        const int dy = t % 3; t /= 3;
        const int ci = t & 15, co = t >> 4;
        const float v = wgt[((co * CMID + ci) * 3 + dy) * 3 + dx];
        __nv_bfloat16 h = __float2bfloat16_rn(v);
        __nv_bfloat16 l = __float2bfloat16_rn(v - __bfloat162float(h));
        const uint32_t a = s32 + BBASE + dy * BDY + co * 112 + (dx * 16 + ci) * 2;
        sts16(a, (uint16_t)__bfloat16_as_ushort(h));
        sts16(a + BLO, (uint16_t)__bfloat16_as_ushort(l));
    }
    {   // prologue: rows y0-1 .. y0+2
        uint32_t pv[2][4];
        #pragma unroll 1
        for (int d = -1; d <= 2; ++d) {
            const int yin = y0 + d;
            if (yin < 0 || yin >= H) continue;
            stage_load_row<NTT>(in, b, yin, x0, tid, pv);
            stage_store_row<NTT>(s32, yin, tid, pv);
        }
    }
    __syncthreads();

    const int wm = wid & 1, wn = wid >> 1;
    float sacc[NF][2] = {}, qacc[NF][2] = {};

    #pragma unroll 1
    for (int i = 0; i < NITER; ++i) {
        const int y = y0 + 2 * i;
        // prefetch next two input rows (LDG early, STS after compute)
        uint32_t pf0[2][4], pf1[2][4];
        const bool h0 = (i + 1 < NITER) && (y + 3 < H);
        const bool h1 = (i + 1 < NITER) && (y + 4 < H);
        if (h0) stage_load_row<NTT>(in, b, y + 3, x0, tid, pf0);
        if (h1) stage_load_row<NTT>(in, b, y + 4, x0, tid, pf1);

        float acc0[NF][4], acc1[NF][4];
        #pragma unroll
        for (int nf = 0; nf < NF; ++nf)
            #pragma unroll
            for (int r = 0; r < 4; ++r) { acc0[nf][r] = 0.f; acc1[nf][r] = 0.f; }

        #pragma unroll
        for (int ks = 0; ks < 3; ++ks) {
            uint32_t bph[NF][2], bpl[NF][2];   // Bprev (dy = ar-1)
            #pragma unroll
            for (int ar = 0; ar < 4; ++ar) {
                const int ga = y - 1 + ar;
                const bool va = (ga >= 0) && (ga < H);
                uint32_t ah[4], al[4];
                if (va) {
                    const uint32_t A0 = s32 + (uint32_t)(ga % 6) * ASLOT;
                    const uint32_t r0 = A0 +
                        (uint32_t)((wm * 16 + g) * 112 + ks * 32 + tig * 4);
                    const uint32_t r1 = r0 + 8 * 112;
                    ah[0] = lds32(r0);        ah[1] = lds32(r1);
                    ah[2] = lds32(r0 + 16);   ah[3] = lds32(r1 + 16);
                    al[0] = lds32(r0 + ALO);  al[1] = lds32(r1 + ALO);
                    al[2] = lds32(r0 + ALO + 16);
                    al[3] = lds32(r1 + ALO + 16);
                }
                uint32_t bch[NF][2], bcl[NF][2];
                if (ar < 3) {
                    const uint32_t B0 = s32 + BBASE + ar * BDY;
                    #pragma unroll
                    for (int nf = 0; nf < NF; ++nf) {
                        const uint32_t c0 = B0 +
                            (uint32_t)((wn * (NF * 8) + nf * 8 + g) * 112 +
                                       ks * 32 + tig * 4);
                        bch[nf][0] = lds32(c0);       bch[nf][1] = lds32(c0 + 16);
                        bcl[nf][0] = lds32(c0 + BLO); bcl[nf][1] = lds32(c0 + BLO + 16);
                    }
                }
                if (va && ar < 3) {
                    #pragma unroll
                    for (int nf = 0; nf < NF; ++nf) {
                        mma_bf16(acc0[nf], ah, bch[nf]);
                        mma_bf16(acc0[nf], ah, bcl[nf]);
                        mma_bf16(acc0[nf], al, bch[nf]);
                    }
                }
                if (va && ar > 0) {
                    #pragma unroll
                    for (int nf = 0; nf < NF; ++nf) {
                        mma_bf16(acc1[nf], ah, bph[nf]);
                        mma_bf16(acc1[nf], ah, bpl[nf]);
                        mma_bf16(acc1[nf], al, bph[nf]);
                    }
                }
                if (ar < 3) {
                    #pragma unroll
                    for (int nf = 0; nf < NF; ++nf) {
                        bph[nf][0] = bch[nf][0]; bph[nf][1] = bch[nf][1];
                        bpl[nf][0] = bcl[nf][0]; bpl[nf][1] = bcl[nf][1];
                    }
                }
            }
        }

        // epilogue: rows y (acc0) and y+1 (acc1)
        const int x = x0 + wm * 16 + g;
        #pragma unroll
        for (int nf = 0; nf < NF; ++nf) {
            const int co = wn * (NF * 8) + nf * 8 + tig * 2;
            #pragma unroll
            for (int row = 0; row < 2; ++row) {
                const float* a4 = row ? acc1[nf] : acc0[nf];
                const size_t base =
                    (((size_t)b * CO + co) * H + (y + row)) * W + x;
                const float v0 = a4[0], v1 = a4[1], v2 = a4[2], v3 = a4[3];
                if (OUTF32) {
                    float* p0 = (float*)outv + base;
                    float* p1 = p0 + (size_t)H * W;
                    p0[0] = v0; p1[0] = v1; p0[8] = v2; p1[8] = v3;
                } else {
                    uint32_t* p0 = (uint32_t*)outv + base;
                    uint32_t* p1 = p0 + (size_t)H * W;
                    p0[0] = packhl(v0); p1[0] = packhl(v1);
                    p0[8] = packhl(v2); p1[8] = packhl(v3);
                }
                if (STATS) {
                    sacc[nf][0] += v0 + v2;
                    sacc[nf][1] += v1 + v3;
                    qacc[nf][0] = fmaf(v0, v0, fmaf(v2, v2, qacc[nf][0]));
                    qacc[nf][1] = fmaf(v1, v1, fmaf(v3, v3, qacc[nf][1]));
                }
            }
        }
        if (h0) stage_store_row<NTT>(s32, y + 3, tid, pf0);
        if (h1) stage_store_row<NTT>(s32, y + 4, tid, pf1);
        __syncthreads();
    }

    if (STATS) {
        #pragma unroll
        for (int nf = 0; nf < NF; ++nf)
            #pragma unroll
            for (int j = 0; j < 2; ++j) {
                float s = sacc[nf][j], q = qacc[nf][j];
                #pragma unroll
                for (int o = 4; o < 32; o <<= 1) {
                    s += __shfl_xor_sync(0xffffffffu, s, o);
                    q += __shfl_xor_sync(0xffffffffu, q, o);
                }
                if (g == 0) {
                    const int c = wn * (NF * 8) + nf * 8 + tig * 2 + j;
                    atomicAdd(&sstats[c], s);
                    atomicAdd(&sstats[COUT + c], q);
                }
            }
        __syncthreads();
        if (tid < 128) atomicAdd(&g_stats[tid], sstats[tid]);
    }
}

// ---- scalar tiled conv (conv1), packed hi/lo NCHW output -------------------
template <int CI, int CO, int TH, int TW>
__global__ void __launch_bounds__(256, 2)
conv3x3_tile(const float* __restrict__ in, const float* __restrict__ wgt,
             uint32_t* __restrict__ out) {
    constexpr int NTT = 256, NPX = TH * TW / 8, NCG = CO / 8;
    static_assert(NPX * NCG == NTT, "shape");
    constexpr int IH = TH + 2, IW = TW + 2, RS = (IW + 3) & ~3;
    extern __shared__ float fsm[];
    float* s_in = fsm;
    float* s_w  = fsm + CI * IH * RS;

    const int tid = threadIdx.x;
    int bid = blockIdx.x;
    const int tx = bid % (W / TW); bid /= (W / TW);
    const int ty = bid % (H / TH); bid /= (H / TH);
    const int b = bid;

    for (int i = tid; i < CI * 9 * CO; i += NTT) {
        const int k = i / CO, co = i - k * CO, ci = k / 9, t = k - ci * 9;
        s_w[i] = wgt[(co * CI + ci) * 9 + t];
    }
    const float* inb = in + (size_t)b * CI * H * W;
    const int gy0 = ty * TH - 1, gx0 = tx * TW - 1;
    for (int i = tid; i < CI * IH * IW; i += NTT) {
        const int ci = i / (IH * IW);
        int r = i - ci * IH * IW;
        const int y = r / IW, x = r - y * IW;
        const int gy = gy0 + y, gx = gx0 + x;
        float v = 0.f;
        if (gy >= 0 && gy < H && gx >= 0 && gx < W)
            v = inb[(ci * H + gy) * W + gx];
        s_in[(ci * IH + y) * RS + x] = v;
    }
    __syncthreads();

    const int px = tid % NPX, cg = tid / NPX;
    const int py = px / (TW / 8), x0 = (px - py * (TW / 8)) * 8, co0 = cg * 8;
    float acc[8][8];
    #pragma unroll
    for (int i = 0; i < 8; ++i)
        #pragma unroll
        for (int j = 0; j < 8; ++j) acc[i][j] = 0.f;

    #pragma unroll 1
    for (int ci = 0; ci < CI; ++ci)
        #pragma unroll
        for (int dy = 0; dy < 3; ++dy) {
            const float* rp = &s_in[(ci * IH + py + dy) * RS + x0];
            float rr[10];
            const float4 a0 = *reinterpret_cast<const float4*>(rp);
            const float4 a1 = *reinterpret_cast<const float4*>(rp + 4);
            const float2 a2 = *reinterpret_cast<const float2*>(rp + 8);
            rr[0]=a0.x; rr[1]=a0.y; rr[2]=a0.z; rr[3]=a0.w;
            rr[4]=a1.x; rr[5]=a1.y; rr[6]=a1.z; rr[7]=a1.w;
            rr[8]=a2.x; rr[9]=a2.y;
            #pragma unroll
            for (int dx = 0; dx < 3; ++dx) {
                const float* wp = &s_w[(ci * 9 + dy * 3 + dx) * CO + co0];
                const float4 w0 = *reinterpret_cast<const float4*>(wp);
                const float4 w1 = *reinterpret_cast<const float4*>(wp + 4);
                const float wv[8] = {w0.x, w0.y, w0.z, w0.w, w1.x, w1.y, w1.z, w1.w};
                #pragma unroll
                for (int co = 0; co < 8; ++co)
                    #pragma unroll
                    for (int p = 0; p < 8; ++p)
                        acc[co][p] = fmaf(wv[co], rr[p + dx], acc[co][p]);
            }
        }
    uint32_t* outb = out + (size_t)b * CO * H * W;
    const int oy = ty * TH + py, ox = tx * TW + x0;
    #pragma unroll
    for (int co = 0; co < 8; ++co) {
        uint32_t* op = &outb[((size_t)(co0 + co) * H + oy) * W + ox];
        uint4 u0, u1;
        u0.x = packhl(acc[co][0]); u0.y = packhl(acc[co][1]);
        u0.z = packhl(acc[co][2]); u0.w = packhl(acc[co][3]);
        u1.x = packhl(acc[co][4]); u1.y = packhl(acc[co][5]);
        u1.z = packhl(acc[co][6]); u1.w = packhl(acc[co][7]);
        *reinterpret_cast<uint4*>(op)     = u0;
        *reinterpret_cast<uint4*>(op + 4) = u1;
    }
}

__global__ void zero_stats_kernel() {
    if (threadIdx.x < 2 * COUT) g_stats[threadIdx.x] = 0.f;
}
__global__ void bn_finalize_kernel(const float* __restrict__ gamma,
                                   const float* __restrict__ beta) {
    const int c = threadIdx.x;
    if (c >= COUT) return;
    const float n = (float)B * H * W;
    const float mean = g_stats[c] / n;
    const float var  = g_stats[COUT + c] / n - mean * mean;
    const float sc   = gamma[c] * rsqrtf(var + BN_EPS);
    g_scale[c] = sc;
    g_shift[c] = beta[c] - mean * sc;
}
__global__ void bn_apply_kernel(float* __restrict__ out) {
    const int idx = blockIdx.x * blockDim.x + threadIdx.x;
    const int c = (idx >> 14) & (COUT - 1);
    const float sc = g_scale[c], sh = g_shift[c];
    float4 v = reinterpret_cast<float4*>(out)[idx];
    v.x = fmaf(v.x, sc, sh); v.y = fmaf(v.y, sc, sh);
    v.z = fmaf(v.z, sc, sh); v.w = fmaf(v.w, sc, sh);
    reinterpret_cast<float4*>(out)[idx] = v;
}

extern "C" void kernel_launch(void* const* d_in, const int* in_sizes, int n_in,
                              void* d_out, int out_size) {
    (void)in_sizes; (void)n_in; (void)out_size;
    const float* x     = (const float*)d_in[0];
    const float* w1    = (const float*)d_in[1];
    const float* w2    = (const float*)d_in[2];
    const float* w3    = (const float*)d_in[3];
    const float* gamma = (const float*)d_in[4];
    const float* beta  = (const float*)d_in[5];
    float* out = (float*)d_out;

    uint32_t *h1, *h2;
    cudaGetSymbolAddress((void**)&h1, g_h1);
    cudaGetSymbolAddress((void**)&h2, g_h2);

    auto* k1 = conv3x3_tile<CIN0, CMID, 32, 32>;
    auto* k2 = conv_mma<16, 2, 1, false, false>;   // 128 thr, 4 blocks/SM
    auto* k3 = conv_mma<64, 4, 2, true,  true>;    // 256 thr, 2 blocks/SM

    constexpr int SM1 = (CIN0 * 34 * 36 + CIN0 * 9 * CMID) * 4;
    constexpr int SM2 = BBASE + 3 * (2 * 16 * 112) + 512;   //  53,760+512
    constexpr int SM3 = BBASE + 3 * (2 * 64 * 112) + 512;   //  86,016+512

    cudaFuncSetAttribute(k1, cudaFuncAttributeMaxDynamicSharedMemorySize, SM1);
    cudaFuncSetAttribute(k2, cudaFuncAttributeMaxDynamicSharedMemorySize, SM2);
    cudaFuncSetAttribute(k3, cudaFuncAttributeMaxDynamicSharedMemorySize, SM3);

    zero_stats_kernel<<<1, 128>>>();
    k1<<<B * (H / 32) * (W / 32), 256, SM1>>>(x, w1, h1);
    k2<<<B * 32 * 8, 128, SM2>>>(h1, w2, h2);
    k3<<<B * 32 * 8, 256, SM3>>>(h2, w3, out);
    bn_finalize_kernel<<<1, 64>>>(gamma, beta);
    bn_apply_kernel<<<(B * COUT * H * W / 4) / 256, 256>>>(out);
}

// round 13
// speedup vs baseline: 1.2668x; 1.2668x over previous
#include <cuda_runtime.h>
#include <cuda_bf16.h>
#include <cstdint>

static constexpr int B = 16, H = 256, W = 256;
static constexpr int CIN0 = 3, CMID = 16, COUT = 64;
static constexpr float BN_EPS = 1e-5f;

// h1/h2 stored pre-split NCHW: (bf16_hi << 16) | bf16_lo per element
__device__ uint32_t g_h1[(size_t)B * CMID * H * W];
__device__ uint32_t g_h2[(size_t)B * CMID * H * W];
__device__ float g_stats[2 * COUT];
__device__ float g_scale[COUT];
__device__ float g_shift[COUT];

// ---- helpers ---------------------------------------------------------------
__device__ __forceinline__ uint32_t smem_u32(const void* p) {
    uint32_t a;
    asm("{ .reg .u64 t; cvta.to.shared.u64 t, %1; cvt.u32.u64 %0, t; }"
        : "=r"(a) : "l"(p));
    return a;
}
__device__ __forceinline__ void sts64(uint32_t a, uint32_t x, uint32_t y) {
    asm volatile("st.shared.v2.u32 [%0], {%1,%2};" :: "r"(a), "r"(x), "r"(y));
}
__device__ __forceinline__ void sts16(uint32_t a, uint16_t v) {
    asm volatile("st.shared.u16 [%0], %1;" :: "r"(a), "h"(v));
}
__device__ __forceinline__ uint32_t lds32(uint32_t a) {
    uint32_t v;
    asm volatile("ld.shared.b32 %0, [%1];" : "=r"(v) : "r"(a));
    return v;
}
__device__ __forceinline__ uint32_t packhl(float v) {
    __nv_bfloat16 h = __float2bfloat16_rn(v);
    float lo = v - __bfloat162float(h);
    __nv_bfloat16 l = __float2bfloat16_rn(lo);
    return ((uint32_t)__bfloat16_as_ushort(h) << 16) |
           (uint32_t)__bfloat16_as_ushort(l);
}
__device__ __forceinline__ void mma_bf16(float d[4], const uint32_t a[4],
                                         const uint32_t b[2]) {
    asm volatile(
        "mma.sync.aligned.m16n8k16.row.col.f32.bf16.bf16.f32 "
        "{%0,%1,%2,%3},{%4,%5,%6,%7},{%8,%9},{%0,%1,%2,%3};"
        : "+f"(d[0]), "+f"(d[1]), "+f"(d[2]), "+f"(d[3])
        : "r"(a[0]), "r"(a[1]), "r"(a[2]), "r"(a[3]), "r"(b[0]), "r"(b[1]));
}

// ---- tensor-core 3x3 conv (16 in-ch), split-bf16 3-term --------------------
// Tile: 128 px (M) x CO. A per input row stored UNSHIFTED: [130 xl][16 ci],
// row stride 48 B (conflict-free: 12g+tig distinct mod 32); the dx shift is
// applied as an address offset (+ks*48) at fragment-load time. hi half then
// lo half per slot; ring of 4 rows. B per dy: [CO][48], stride 112 B, hi+lo.
static constexpr int AXS   = 48;                // bytes per xl position
static constexpr int ALO   = 132 * AXS;         // 6336, lo half offset
static constexpr int ASLOT = 2 * ALO;           // 12672 per row
static constexpr int BBASE = 4 * ASLOT;         // 50688
static constexpr int NY    = 8;
static constexpr int NT    = 256;
static constexpr int NITEM = 520;               // 130 xl * 4 ci-groups

__device__ __forceinline__ void stage_load(const uint32_t* in, int b, int yin,
                                           int x0, int tid, uint32_t v[3][4]) {
    #pragma unroll
    for (int j = 0; j < 3; ++j) {
        v[j][0] = v[j][1] = v[j][2] = v[j][3] = 0;
        const int it = tid + j * NT;
        if (it >= NITEM) continue;
        const int xl = it >> 2, cig = it & 3, xin = x0 - 1 + xl;
        if (xin >= 0 && xin < W) {
            const uint32_t* p =
                in + (((size_t)b * CMID + cig * 4) * H + yin) * W + xin;
            const size_t st = (size_t)H * W;
            v[j][0] = p[0]; v[j][1] = p[st];
            v[j][2] = p[2 * st]; v[j][3] = p[3 * st];
        }
    }
}
__device__ __forceinline__ void stage_store(uint32_t s32, int yin, int tid,
                                            const uint32_t v[3][4]) {
    const uint32_t Ah = s32 + (uint32_t)(yin & 3) * ASLOT;
    #pragma unroll
    for (int j = 0; j < 3; ++j) {
        const int it = tid + j * NT;
        if (it >= NITEM) continue;
        const int xl = it >> 2, cig = it & 3;
        const uint32_t h0 = __byte_perm(v[j][0], v[j][1], 0x7632);
        const uint32_t h1 = __byte_perm(v[j][2], v[j][3], 0x7632);
        const uint32_t l0 = __byte_perm(v[j][0], v[j][1], 0x5410);
        const uint32_t l1 = __byte_perm(v[j][2], v[j][3], 0x5410);
        const uint32_t off = (uint32_t)(xl * AXS + cig * 8);
        sts64(Ah + off, h0, h1);
        sts64(Ah + ALO + off, l0, l1);
    }
}

// Warp grid WM x WN, per-warp fragments MF x NF.
// WM*MF*16 == 128, WN*NF*8 == CO, WM*WN == 8 (256 threads).
template <int CO, int WM, int WN, int MF, int NF, bool STATS, bool OUTF32>
__global__ void __launch_bounds__(NT, 2)
conv_mma(const uint32_t* __restrict__ in, const float* __restrict__ wgt,
         void* __restrict__ outv) {
    static_assert(WM * MF * 16 == 128 && WN * NF * 8 == CO && WM * WN == 8, "");
    constexpr int BLO  = CO * 112;
    constexpr int BDY  = 2 * BLO;
    constexpr int SOFF = BBASE + 3 * BDY;

    extern __shared__ char sm[];
    const uint32_t s32 = smem_u32(sm);
    float* sstats = (float*)(sm + SOFF);
    const int tid = threadIdx.x, wid = tid >> 5, lid = tid & 31;
    const int g = lid >> 2, tig = lid & 3;
    int bid = blockIdx.x;
    const int xs = bid & 1, ys = (bid >> 1) & 31, b = bid >> 6;
    const int x0 = xs * 128, y0 = ys * NY;

    if (STATS && tid < 128) sstats[tid] = 0.f;
    for (int i = tid; i < CO * CMID * 9; i += NT) {      // weights -> B tiles
        const int dx = i % 3; int t = i / 3;
        const int dy = t % 3; t /= 3;
        const int ci = t & 15, co = t >> 4;
        const float v = wgt[((co * CMID + ci) * 3 + dy) * 3 + dx];
        __nv_bfloat16 h = __float2bfloat16_rn(v);
        __nv_bfloat16 l = __float2bfloat16_rn(v - __bfloat162float(h));
        const uint32_t a = s32 + BBASE + dy * BDY + co * 112 + (dx * 16 + ci) * 2;
        sts16(a, (uint16_t)__bfloat16_as_ushort(h));
        sts16(a + BLO, (uint16_t)__bfloat16_as_ushort(l));
    }
    {   // prologue: rows y0-1, y0, y0+1
        uint32_t pv[3][4];
        if (y0 > 0) {
            stage_load(in, b, y0 - 1, x0, tid, pv);
            stage_store(s32, y0 - 1, tid, pv);
        }
        stage_load(in, b, y0, x0, tid, pv);
        stage_store(s32, y0, tid, pv);
        stage_load(in, b, y0 + 1, x0, tid, pv);
        stage_store(s32, y0 + 1, tid, pv);
    }
    __syncthreads();

    const int wm = wid % WM, wn = wid / WM;
    float sacc[NF][2] = {}, qacc[NF][2] = {};

    for (int i = 0; i < NY; ++i) {
        const int y = y0 + i;
        const bool have = (y + 2 < H);
        uint32_t pf[3][4];
        if (have) stage_load(in, b, y + 2, x0, tid, pf);  // LDG early

        float acc[MF][NF][4];
        #pragma unroll
        for (int mf = 0; mf < MF; ++mf)
            #pragma unroll
            for (int nf = 0; nf < NF; ++nf)
                #pragma unroll
                for (int r = 0; r < 4; ++r) acc[mf][nf][r] = 0.f;

        #pragma unroll
        for (int dy = 0; dy < 3; ++dy) {
            const int yin = y - 1 + dy;
            if (yin < 0 || yin >= H) continue;
            const uint32_t A0 = s32 + (uint32_t)(yin & 3) * ASLOT;
            const uint32_t B0 = s32 + BBASE + dy * BDY;
            #pragma unroll
            for (int ks = 0; ks < 3; ++ks) {
                uint32_t ah[MF][4], al[MF][4], bh[NF][2], bl[NF][2];
                #pragma unroll
                for (int mf = 0; mf < MF; ++mf) {
                    // unshifted A: xl = px + ks, px = wm*(MF*16)+mf*16+g
                    const uint32_t r0 = A0 +
                        (uint32_t)((wm * (MF * 16) + mf * 16 + g + ks) * AXS +
                                   tig * 4);
                    const uint32_t r1 = r0 + 8 * AXS;
                    ah[mf][0] = lds32(r0);        ah[mf][1] = lds32(r1);
                    ah[mf][2] = lds32(r0 + 16);   ah[mf][3] = lds32(r1 + 16);
                    al[mf][0] = lds32(r0 + ALO);  al[mf][1] = lds32(r1 + ALO);
                    al[mf][2] = lds32(r0 + ALO + 16);
                    al[mf][3] = lds32(r1 + ALO + 16);
                }
                #pragma unroll
                for (int nf = 0; nf < NF; ++nf) {
                    const uint32_t c0 = B0 +
                        (uint32_t)((wn * (NF * 8) + nf * 8 + g) * 112 +
                                   ks * 32 + tig * 4);
                    bh[nf][0] = lds32(c0);        bh[nf][1] = lds32(c0 + 16);
                    bl[nf][0] = lds32(c0 + BLO);  bl[nf][1] = lds32(c0 + BLO + 16);
                }
                #pragma unroll
                for (int mf = 0; mf < MF; ++mf)
                    #pragma unroll
                    for (int nf = 0; nf < NF; ++nf) {
                        mma_bf16(acc[mf][nf], ah[mf], bh[nf]);
                        mma_bf16(acc[mf][nf], ah[mf], bl[nf]);
                        mma_bf16(acc[mf][nf], al[mf], bh[nf]);
                    }
            }
        }

        #pragma unroll
        for (int mf = 0; mf < MF; ++mf) {
            const int x = x0 + wm * (MF * 16) + mf * 16 + g;
            #pragma unroll
            for (int nf = 0; nf < NF; ++nf) {
                const int co = wn * (NF * 8) + nf * 8 + tig * 2;
                const size_t base = (((size_t)b * CO + co) * H + y) * W + x;
                const float v0 = acc[mf][nf][0], v1 = acc[mf][nf][1];
                const float v2 = acc[mf][nf][2], v3 = acc[mf][nf][3];
                if (OUTF32) {
                    float* p0 = (float*)outv + base;
                    float* p1 = p0 + (size_t)H * W;
                    p0[0] = v0; p1[0] = v1; p0[8] = v2; p1[8] = v3;
                } else {
                    uint32_t* p0 = (uint32_t*)outv + base;
                    uint32_t* p1 = p0 + (size_t)H * W;
                    p0[0] = packhl(v0); p1[0] = packhl(v1);
                    p0[8] = packhl(v2); p1[8] = packhl(v3);
                }
                if (STATS) {
                    sacc[nf][0] += v0 + v2;
                    sacc[nf][1] += v1 + v3;
                    qacc[nf][0] = fmaf(v0, v0, fmaf(v2, v2, qacc[nf][0]));
                    qacc[nf][1] = fmaf(v1, v1, fmaf(v3, v3, qacc[nf][1]));
                }
            }
        }
        if (have) stage_store(s32, y + 2, tid, pf);  // slot (y+2)&3 disjoint
        __syncthreads();
    }

    if (STATS) {
        #pragma unroll
        for (int nf = 0; nf < NF; ++nf)
            #pragma unroll
            for (int j = 0; j < 2; ++j) {
                float s = sacc[nf][j], q = qacc[nf][j];
                #pragma unroll
                for (int o = 4; o < 32; o <<= 1) {
                    s += __shfl_xor_sync(0xffffffffu, s, o);
                    q += __shfl_xor_sync(0xffffffffu, q, o);
                }
                if (g == 0) {
                    const int c = wn * (NF * 8) + nf * 8 + tig * 2 + j;
                    atomicAdd(&sstats[c], s);
                    atomicAdd(&sstats[COUT + c], q);
                }
            }
        __syncthreads();
        if (tid < 128) atomicAdd(&g_stats[tid], sstats[tid]);
    }
}

// ---- scalar tiled conv (conv1), packed hi/lo NCHW output -------------------
template <int CI, int CO, int TH, int TW>
__global__ void __launch_bounds__(256, 2)
conv3x3_tile(const float* __restrict__ in, const float* __restrict__ wgt,
             uint32_t* __restrict__ out) {
    constexpr int NTT = 256, NPX = TH * TW / 8, NCG = CO / 8;
    static_assert(NPX * NCG == NTT, "shape");
    constexpr int IH = TH + 2, IW = TW + 2, RS = (IW + 3) & ~3;
    extern __shared__ float fsm[];
    float* s_in = fsm;
    float* s_w  = fsm + CI * IH * RS;

    const int tid = threadIdx.x;
    int bid = blockIdx.x;
    const int tx = bid % (W / TW); bid /= (W / TW);
    const int ty = bid % (H / TH); bid /= (H / TH);
    const int b = bid;

    for (int i = tid; i < CI * 9 * CO; i += NTT) {
        const int k = i / CO, co = i - k * CO, ci = k / 9, t = k - ci * 9;
        s_w[i] = wgt[(co * CI + ci) * 9 + t];
    }
    const float* inb = in + (size_t)b * CI * H * W;
    const int gy0 = ty * TH - 1, gx0 = tx * TW - 1;
    for (int i = tid; i < CI * IH * IW; i += NTT) {
        const int ci = i / (IH * IW);
        int r = i - ci * IH * IW;
        const int y = r / IW, x = r - y * IW;
        const int gy = gy0 + y, gx = gx0 + x;
        float v = 0.f;
        if (gy >= 0 && gy < H && gx >= 0 && gx < W)
            v = inb[(ci * H + gy) * W + gx];
        s_in[(ci * IH + y) * RS + x] = v;
    }
    __syncthreads();

    const int px = tid % NPX, cg = tid / NPX;
    const int py = px / (TW / 8), x0 = (px - py * (TW / 8)) * 8, co0 = cg * 8;
    float acc[8][8];
    #pragma unroll
    for (int i = 0; i < 8; ++i)
        #pragma unroll
        for (int j = 0; j < 8; ++j) acc[i][j] = 0.f;

    #pragma unroll 1
    for (int ci = 0; ci < CI; ++ci)
        #pragma unroll
        for (int dy = 0; dy < 3; ++dy) {
            const float* rp = &s_in[(ci * IH + py + dy) * RS + x0];
            float rr[10];
            const float4 a0 = *reinterpret_cast<const float4*>(rp);
            const float4 a1 = *reinterpret_cast<const float4*>(rp + 4);
            const float2 a2 = *reinterpret_cast<const float2*>(rp + 8);
            rr[0]=a0.x; rr[1]=a0.y; rr[2]=a0.z; rr[3]=a0.w;
            rr[4]=a1.x; rr[5]=a1.y; rr[6]=a1.z; rr[7]=a1.w;
            rr[8]=a2.x; rr[9]=a2.y;
            #pragma unroll
            for (int dx = 0; dx < 3; ++dx) {
                const float* wp = &s_w[(ci * 9 + dy * 3 + dx) * CO + co0];
                const float4 w0 = *reinterpret_cast<const float4*>(wp);
                const float4 w1 = *reinterpret_cast<const float4*>(wp + 4);
                const float wv[8] = {w0.x, w0.y, w0.z, w0.w, w1.x, w1.y, w1.z, w1.w};
                #pragma unroll
                for (int co = 0; co < 8; ++co)
                    #pragma unroll
                    for (int p = 0; p < 8; ++p)
                        acc[co][p] = fmaf(wv[co], rr[p + dx], acc[co][p]);
            }
        }
    uint32_t* outb = out + (size_t)b * CO * H * W;
    const int oy = ty * TH + py, ox = tx * TW + x0;
    #pragma unroll
    for (int co = 0; co < 8; ++co) {
        uint32_t* op = &outb[((size_t)(co0 + co) * H + oy) * W + ox];
        uint4 u0, u1;
        u0.x = packhl(acc[co][0]); u0.y = packhl(acc[co][1]);
        u0.z = packhl(acc[co][2]); u0.w = packhl(acc[co][3]);
        u1.x = packhl(acc[co][4]); u1.y = packhl(acc[co][5]);
        u1.z = packhl(acc[co][6]); u1.w = packhl(acc[co][7]);
        *reinterpret_cast<uint4*>(op)     = u0;
        *reinterpret_cast<uint4*>(op + 4) = u1;
    }
}

__global__ void zero_stats_kernel() {
    if (threadIdx.x < 2 * COUT) g_stats[threadIdx.x] = 0.f;
}
__global__ void bn_finalize_kernel(const float* __restrict__ gamma,
                                   const float* __restrict__ beta) {
    const int c = threadIdx.x;
    if (c >= COUT) return;
    const float n = (float)B * H * W;
    const float mean = g_stats[c] / n;
    const float var  = g_stats[COUT + c] / n - mean * mean;
    const float sc   = gamma[c] * rsqrtf(var + BN_EPS);
    g_scale[c] = sc;
    g_shift[c] = beta[c] - mean * sc;
}
__global__ void bn_apply_kernel(float* __restrict__ out) {
    const int idx = blockIdx.x * blockDim.x + threadIdx.x;
    const int c = (idx >> 14) & (COUT - 1);
    const float sc = g_scale[c], sh = g_shift[c];
    float4 v = reinterpret_cast<float4*>(out)[idx];
    v.x = fmaf(v.x, sc, sh); v.y = fmaf(v.y, sc, sh);
    v.z = fmaf(v.z, sc, sh); v.w = fmaf(v.w, sc, sh);
    reinterpret_cast<float4*>(out)[idx] = v;
}

extern "C" void kernel_launch(void* const* d_in, const int* in_sizes, int n_in,
                              void* d_out, int out_size) {
    (void)in_sizes; (void)n_in; (void)out_size;
    const float* x     = (const float*)d_in[0];
    const float* w1    = (const float*)d_in[1];
    const float* w2    = (const float*)d_in[2];
    const float* w3    = (const float*)d_in[3];
    const float* gamma = (const float*)d_in[4];
    const float* beta  = (const float*)d_in[5];
    float* out = (float*)d_out;

    uint32_t *h1, *h2;
    cudaGetSymbolAddress((void**)&h1, g_h1);
    cudaGetSymbolAddress((void**)&h2, g_h2);

    auto* k1 = conv3x3_tile<CIN0, CMID, 32, 32>;
    auto* k2 = conv_mma<16, 4, 2, 2, 1, false, false>;   // h1 -> packed h2
    auto* k3 = conv_mma<64, 4, 2, 2, 4, true,  true>;    // h2 -> fp32 out

    constexpr int SM1 = (CIN0 * 34 * 36 + CIN0 * 9 * CMID) * 4;
    constexpr int SM2 = BBASE + 3 * (2 * 16 * 112) + 512;   //  61,952
    constexpr int SM3 = BBASE + 3 * (2 * 64 * 112) + 512;   //  94,208

    cudaFuncSetAttribute(k1, cudaFuncAttributeMaxDynamicSharedMemorySize, SM1);
    cudaFuncSetAttribute(k2, cudaFuncAttributeMaxDynamicSharedMemorySize, SM2);
    cudaFuncSetAttribute(k3, cudaFuncAttributeMaxDynamicSharedMemorySize, SM3);

    zero_stats_kernel<<<1, 128>>>();
    k1<<<B * (H / 32) * (W / 32), 256, SM1>>>(x, w1, h1);
    k2<<<B * 32 * 2, NT, SM2>>>(h1, w2, h2);
    k3<<<B * 32 * 2, NT, SM3>>>(h2, w3, out);
    bn_finalize_kernel<<<1, 64>>>(gamma, beta);
    bn_apply_kernel<<<(B * COUT * H * W / 4) / 256, 256>>>(out);
}

// round 14
// speedup vs baseline: 1.6129x; 1.2732x over previous
#include <cuda_runtime.h>
#include <cuda_fp16.h>
#include <cstdint>

static constexpr int B = 16, H = 256, W = 256;
static constexpr int CIN0 = 3, CMID = 16, COUT = 64;
static constexpr float BN_EPS = 1e-5f;

// h1/h2: fp16, stored as __half2 ci-pair planes: [b][ci/2][y][x] (uint32)
__device__ uint32_t g_h1[(size_t)B * (CMID / 2) * H * W];
__device__ uint32_t g_h2[(size_t)B * (CMID / 2) * H * W];
__device__ float g_stats[2 * COUT];
__device__ float g_scale[COUT];
__device__ float g_shift[COUT];

// ---- helpers ---------------------------------------------------------------
__device__ __forceinline__ uint32_t smem_u32(const void* p) {
    uint32_t a;
    asm("{ .reg .u64 t; cvta.to.shared.u64 t, %1; cvt.u32.u64 %0, t; }"
        : "=r"(a) : "l"(p));
    return a;
}
__device__ __forceinline__ void sts64(uint32_t a, uint32_t x, uint32_t y) {
    asm volatile("st.shared.v2.u32 [%0], {%1,%2};" :: "r"(a), "r"(x), "r"(y));
}
__device__ __forceinline__ void sts16(uint32_t a, uint16_t v) {
    asm volatile("st.shared.u16 [%0], %1;" :: "r"(a), "h"(v));
}
__device__ __forceinline__ uint32_t lds32(uint32_t a) {
    uint32_t v;
    asm volatile("ld.shared.b32 %0, [%1];" : "=r"(v) : "r"(a));
    return v;
}
__device__ __forceinline__ uint32_t packh2(float lo, float hi) {
    const __half h0 = __float2half_rn(lo), h1 = __float2half_rn(hi);
    return ((uint32_t)__half_as_ushort(h1) << 16) |
           (uint32_t)__half_as_ushort(h0);
}
// baseline-PTX fp16 tensor-core mma (sm_80+)
__device__ __forceinline__ void mma_f16(float d[4], const uint32_t a[4],
                                        const uint32_t b[2]) {
    asm volatile(
        "mma.sync.aligned.m16n8k16.row.col.f32.f16.f16.f32 "
        "{%0,%1,%2,%3},{%4,%5,%6,%7},{%8,%9},{%0,%1,%2,%3};"
        : "+f"(d[0]), "+f"(d[1]), "+f"(d[2]), "+f"(d[3])
        : "r"(a[0]), "r"(a[1]), "r"(a[2]), "r"(a[3]), "r"(b[0]), "r"(b[1]));
}

// ---- tensor-core 3x3 conv (16 in-ch), fp16 acts / split-fp16 weights -------
// A per input row UNSHIFTED: [130 xl][16 ci fp16], row stride 48 B
// (conflict-free: banks 12g+tig distinct mod 32); dx shift = +ks*48 address
// offset at fragment load. Ring of 4 rows. B per dy: [CO][48 fp16], stride
// 112 B, hi half + lo half (weight residual). 2 MMAs per step: A*Bh + A*Bl.
static constexpr int AXS   = 48;
static constexpr int ASLOT = 132 * AXS;         // 6336 per row (single fp16)
static constexpr int BBASE = 4 * ASLOT;         // 25344
static constexpr int NY    = 8;
static constexpr int NT    = 256;
static constexpr int NITEM = 520;               // 130 xl * 4 ci-groups

__device__ __forceinline__ void stage_load(const uint32_t* in, int b, int yin,
                                           int x0, int tid, uint32_t v[3][2]) {
    #pragma unroll
    for (int j = 0; j < 3; ++j) {
        v[j][0] = v[j][1] = 0;
        const int it = tid + j * NT;
        if (it >= NITEM) continue;
        const int xl = it >> 2, cig = it & 3, xin = x0 - 1 + xl;
        if (xin >= 0 && xin < W) {
            const uint32_t* p =                      // planes cp=2cig, 2cig+1
                in + (((size_t)b * 8 + cig * 2) * H + yin) * W + xin;
            v[j][0] = p[0];
            v[j][1] = p[(size_t)H * W];
        }
    }
}
__device__ __forceinline__ void stage_store(uint32_t s32, int yin, int tid,
                                            const uint32_t v[3][2]) {
    const uint32_t Ah = s32 + (uint32_t)(yin & 3) * ASLOT;
    #pragma unroll
    for (int j = 0; j < 3; ++j) {
        const int it = tid + j * NT;
        if (it >= NITEM) continue;
        const int xl = it >> 2, cig = it & 3;
        sts64(Ah + (uint32_t)(xl * AXS + cig * 8), v[j][0], v[j][1]);
    }
}

// Warp grid WM x WN, per-warp fragments MF x NF.
// WM*MF*16 == 128, WN*NF*8 == CO, WM*WN == 8 (256 threads).
// OUTH2: write __half2 ci-pair planes (conv2); else fp32 NCHW (conv3).
template <int CO, int WM, int WN, int MF, int NF, bool STATS, bool OUTH2>
__global__ void __launch_bounds__(NT, 2)
conv_mma(const uint32_t* __restrict__ in, const float* __restrict__ wgt,
         void* __restrict__ outv) {
    static_assert(WM * MF * 16 == 128 && WN * NF * 8 == CO && WM * WN == 8, "");
    constexpr int BLO  = CO * 112;
    constexpr int BDY  = 2 * BLO;
    constexpr int SOFF = BBASE + 3 * BDY;

    extern __shared__ char sm[];
    const uint32_t s32 = smem_u32(sm);
    float* sstats = (float*)(sm + SOFF);
    const int tid = threadIdx.x, wid = tid >> 5, lid = tid & 31;
    const int g = lid >> 2, tig = lid & 3;
    int bid = blockIdx.x;
    const int xs = bid & 1, ys = (bid >> 1) & 31, b = bid >> 6;
    const int x0 = xs * 128, y0 = ys * NY;

    if (STATS && tid < 128) sstats[tid] = 0.f;
    for (int i = tid; i < CO * CMID * 9; i += NT) {   // weights -> B hi/lo
        const int dx = i % 3; int t = i / 3;
        const int dy = t % 3; t /= 3;
        const int ci = t & 15, co = t >> 4;
        const float v = wgt[((co * CMID + ci) * 3 + dy) * 3 + dx];
        const __half h = __float2half_rn(v);
        const __half l = __float2half_rn(v - __half2float(h));
        const uint32_t a = s32 + BBASE + dy * BDY + co * 112 + (dx * 16 + ci) * 2;
        sts16(a, (uint16_t)__half_as_ushort(h));
        sts16(a + BLO, (uint16_t)__half_as_ushort(l));
    }
    {   // prologue: rows y0-1, y0, y0+1
        uint32_t pv[3][2];
        if (y0 > 0) {
            stage_load(in, b, y0 - 1, x0, tid, pv);
            stage_store(s32, y0 - 1, tid, pv);
        }
        stage_load(in, b, y0, x0, tid, pv);
        stage_store(s32, y0, tid, pv);
        stage_load(in, b, y0 + 1, x0, tid, pv);
        stage_store(s32, y0 + 1, tid, pv);
    }
    __syncthreads();

    const int wm = wid % WM, wn = wid / WM;
    float sacc[NF][2] = {}, qacc[NF][2] = {};

    for (int i = 0; i < NY; ++i) {
        const int y = y0 + i;
        const bool have = (y + 2 < H);
        uint32_t pf[3][2];
        if (have) stage_load(in, b, y + 2, x0, tid, pf);  // LDG early

        float acc[MF][NF][4];
        #pragma unroll
        for (int mf = 0; mf < MF; ++mf)
            #pragma unroll
            for (int nf = 0; nf < NF; ++nf)
                #pragma unroll
                for (int r = 0; r < 4; ++r) acc[mf][nf][r] = 0.f;

        #pragma unroll
        for (int dy = 0; dy < 3; ++dy) {
            const int yin = y - 1 + dy;
            if (yin < 0 || yin >= H) continue;
            const uint32_t A0 = s32 + (uint32_t)(yin & 3) * ASLOT;
            const uint32_t B0 = s32 + BBASE + dy * BDY;
            #pragma unroll
            for (int ks = 0; ks < 3; ++ks) {
                uint32_t a[MF][4], bh[NF][2], bl[NF][2];
                #pragma unroll
                for (int mf = 0; mf < MF; ++mf) {
                    // unshifted A: xl = px + ks
                    const uint32_t r0 = A0 +
                        (uint32_t)((wm * (MF * 16) + mf * 16 + g + ks) * AXS +
                                   tig * 4);
                    const uint32_t r1 = r0 + 8 * AXS;
                    a[mf][0] = lds32(r0);      a[mf][1] = lds32(r1);
                    a[mf][2] = lds32(r0 + 16); a[mf][3] = lds32(r1 + 16);
                }
                #pragma unroll
                for (int nf = 0; nf < NF; ++nf) {
                    const uint32_t c0 = B0 +
                        (uint32_t)((wn * (NF * 8) + nf * 8 + g) * 112 +
                                   ks * 32 + tig * 4);
                    bh[nf][0] = lds32(c0);        bh[nf][1] = lds32(c0 + 16);
                    bl[nf][0] = lds32(c0 + BLO);  bl[nf][1] = lds32(c0 + BLO + 16);
                }
                #pragma unroll
                for (int mf = 0; mf < MF; ++mf)
                    #pragma unroll
                    for (int nf = 0; nf < NF; ++nf) {
                        mma_f16(acc[mf][nf], a[mf], bh[nf]);
                        mma_f16(acc[mf][nf], a[mf], bl[nf]);
                    }
            }
        }

        #pragma unroll
        for (int mf = 0; mf < MF; ++mf) {
            const int x = x0 + wm * (MF * 16) + mf * 16 + g;
            #pragma unroll
            for (int nf = 0; nf < NF; ++nf) {
                const int co = wn * (NF * 8) + nf * 8 + tig * 2;
                const float v0 = acc[mf][nf][0], v1 = acc[mf][nf][1];
                const float v2 = acc[mf][nf][2], v3 = acc[mf][nf][3];
                if (OUTH2) {
                    // pair plane cp = co/2; (v0,v1) = consecutive co at x
                    const int cp = co >> 1;
                    uint32_t* p = (uint32_t*)outv +
                        (((size_t)b * (CO / 2) + cp) * H + y) * W + x;
                    p[0] = packh2(v0, v1);
                    p[8] = packh2(v2, v3);
                } else {
                    const size_t base = (((size_t)b * CO + co) * H + y) * W + x;
                    float* p0 = (float*)outv + base;
                    float* p1 = p0 + (size_t)H * W;
                    p0[0] = v0; p1[0] = v1; p0[8] = v2; p1[8] = v3;
                }
                if (STATS) {
                    sacc[nf][0] += v0 + v2;
                    sacc[nf][1] += v1 + v3;
                    qacc[nf][0] = fmaf(v0, v0, fmaf(v2, v2, qacc[nf][0]));
                    qacc[nf][1] = fmaf(v1, v1, fmaf(v3, v3, qacc[nf][1]));
                }
            }
        }
        if (have) stage_store(s32, y + 2, tid, pf);  // slot (y+2)&3 disjoint
        __syncthreads();
    }

    if (STATS) {
        #pragma unroll
        for (int nf = 0; nf < NF; ++nf)
            #pragma unroll
            for (int j = 0; j < 2; ++j) {
                float s = sacc[nf][j], q = qacc[nf][j];
                #pragma unroll
                for (int o = 4; o < 32; o <<= 1) {
                    s += __shfl_xor_sync(0xffffffffu, s, o);
                    q += __shfl_xor_sync(0xffffffffu, q, o);
                }
                if (g == 0) {
                    const int c = wn * (NF * 8) + nf * 8 + tig * 2 + j;
                    atomicAdd(&sstats[c], s);
                    atomicAdd(&sstats[COUT + c], q);
                }
            }
        __syncthreads();
        if (tid < 128) atomicAdd(&g_stats[tid], sstats[tid]);
    }
}

// ---- scalar tiled conv (conv1), __half2 ci-pair plane output ---------------
template <int CI, int CO, int TH, int TW>
__global__ void __launch_bounds__(256, 2)
conv3x3_tile(const float* __restrict__ in, const float* __restrict__ wgt,
             uint32_t* __restrict__ out) {
    constexpr int NTT = 256, NPX = TH * TW / 8, NCG = CO / 8;
    static_assert(NPX * NCG == NTT, "shape");
    constexpr int IH = TH + 2, IW = TW + 2, RS = (IW + 3) & ~3;
    extern __shared__ float fsm[];
    float* s_in = fsm;
    float* s_w  = fsm + CI * IH * RS;

    const int tid = threadIdx.x;
    int bid = blockIdx.x;
    const int tx = bid % (W / TW); bid /= (W / TW);
    const int ty = bid % (H / TH); bid /= (H / TH);
    const int b = bid;

    for (int i = tid; i < CI * 9 * CO; i += NTT) {
        const int k = i / CO, co = i - k * CO, ci = k / 9, t = k - ci * 9;
        s_w[i] = wgt[(co * CI + ci) * 9 + t];
    }
    const float* inb = in + (size_t)b * CI * H * W;
    const int gy0 = ty * TH - 1, gx0 = tx * TW - 1;
    for (int i = tid; i < CI * IH * IW; i += NTT) {
        const int ci = i / (IH * IW);
        int r = i - ci * IH * IW;
        const int y = r / IW, x = r - y * IW;
        const int gy = gy0 + y, gx = gx0 + x;
        float v = 0.f;
        if (gy >= 0 && gy < H && gx >= 0 && gx < W)
            v = inb[(ci * H + gy) * W + gx];
        s_in[(ci * IH + y) * RS + x] = v;
    }
    __syncthreads();

    const int px = tid % NPX, cg = tid / NPX;
    const int py = px / (TW / 8), x0 = (px - py * (TW / 8)) * 8, co0 = cg * 8;
    float acc[8][8];
    #pragma unroll
    for (int i = 0; i < 8; ++i)
        #pragma unroll
        for (int j = 0; j < 8; ++j) acc[i][j] = 0.f;

    #pragma unroll 1
    for (int ci = 0; ci < CI; ++ci)
        #pragma unroll
        for (int dy = 0; dy < 3; ++dy) {
            const float* rp = &s_in[(ci * IH + py + dy) * RS + x0];
            float rr[10];
            const float4 a0 = *reinterpret_cast<const float4*>(rp);
            const float4 a1 = *reinterpret_cast<const float4*>(rp + 4);
            const float2 a2 = *reinterpret_cast<const float2*>(rp + 8);
            rr[0]=a0.x; rr[1]=a0.y; rr[2]=a0.z; rr[3]=a0.w;
            rr[4]=a1.x; rr[5]=a1.y; rr[6]=a1.z; rr[7]=a1.w;
            rr[8]=a2.x; rr[9]=a2.y;
            #pragma unroll
            for (int dx = 0; dx < 3; ++dx) {
                const float* wp = &s_w[(ci * 9 + dy * 3 + dx) * CO + co0];
                const float4 w0 = *reinterpret_cast<const float4*>(wp);
                const float4 w1 = *reinterpret_cast<const float4*>(wp + 4);
                const float wv[8] = {w0.x, w0.y, w0.z, w0.w, w1.x, w1.y, w1.z, w1.w};
                #pragma unroll
                for (int co = 0; co < 8; ++co)
                    #pragma unroll
                    for (int p = 0; p < 8; ++p)
                        acc[co][p] = fmaf(wv[co], rr[p + dx], acc[co][p]);
            }
        }
    // output: ci-pair planes [b][co/2][y][x] as __half2
    const int oy = ty * TH + py, ox = tx * TW + x0;
    #pragma unroll
    for (int j = 0; j < 4; ++j) {                       // pair (co0+2j, +2j+1)
        uint32_t* op = out +
            (((size_t)b * (CO / 2) + (co0 >> 1) + j) * H + oy) * W + ox;
        uint4 u0, u1;
        u0.x = packh2(acc[2*j][0], acc[2*j+1][0]);
        u0.y = packh2(acc[2*j][1], acc[2*j+1][1]);
        u0.z = packh2(acc[2*j][2], acc[2*j+1][2]);
        u0.w = packh2(acc[2*j][3], acc[2*j+1][3]);
        u1.x = packh2(acc[2*j][4], acc[2*j+1][4]);
        u1.y = packh2(acc[2*j][5], acc[2*j+1][5]);
        u1.z = packh2(acc[2*j][6], acc[2*j+1][6]);
        u1.w = packh2(acc[2*j][7], acc[2*j+1][7]);
        *reinterpret_cast<uint4*>(op)     = u0;
        *reinterpret_cast<uint4*>(op + 4) = u1;
    }
}

__global__ void zero_stats_kernel() {
    if (threadIdx.x < 2 * COUT) g_stats[threadIdx.x] = 0.f;
}
__global__ void bn_finalize_kernel(const float* __restrict__ gamma,
                                   const float* __restrict__ beta) {
    const int c = threadIdx.x;
    if (c >= COUT) return;
    const float n = (float)B * H * W;
    const float mean = g_stats[c] / n;
    const float var  = g_stats[COUT + c] / n - mean * mean;
    const float sc   = gamma[c] * rsqrtf(var + BN_EPS);
    g_scale[c] = sc;
    g_shift[c] = beta[c] - mean * sc;
}
__global__ void bn_apply_kernel(float* __restrict__ out) {
    const int idx = blockIdx.x * blockDim.x + threadIdx.x;
    const int c = (idx >> 14) & (COUT - 1);
    const float sc = g_scale[c], sh = g_shift[c];
    float4 v = reinterpret_cast<float4*>(out)[idx];
    v.x = fmaf(v.x, sc, sh); v.y = fmaf(v.y, sc, sh);
    v.z = fmaf(v.z, sc, sh); v.w = fmaf(v.w, sc, sh);
    reinterpret_cast<float4*>(out)[idx] = v;
}

extern "C" void kernel_launch(void* const* d_in, const int* in_sizes, int n_in,
                              void* d_out, int out_size) {
    (void)in_sizes; (void)n_in; (void)out_size;
    const float* x     = (const float*)d_in[0];
    const float* w1    = (const float*)d_in[1];
    const float* w2    = (const float*)d_in[2];
    const float* w3    = (const float*)d_in[3];
    const float* gamma = (const float*)d_in[4];
    const float* beta  = (const float*)d_in[5];
    float* out = (float*)d_out;

    uint32_t *h1, *h2;
    cudaGetSymbolAddress((void**)&h1, g_h1);
    cudaGetSymbolAddress((void**)&h2, g_h2);

    auto* k1 = conv3x3_tile<CIN0, CMID, 32, 32>;
    auto* k2 = conv_mma<16, 8, 1, 1, 2, false, true>;   // h1 -> half2 h2
    auto* k3 = conv_mma<64, 4, 2, 2, 4, true,  false>;  // h2 -> fp32 out

    constexpr int SM1 = (CIN0 * 34 * 36 + CIN0 * 9 * CMID) * 4;
    constexpr int SM2 = BBASE + 3 * (2 * 16 * 112) + 512;   // 36,608
    constexpr int SM3 = BBASE + 3 * (2 * 64 * 112) + 512;   // 68,864

    cudaFuncSetAttribute(k1, cudaFuncAttributeMaxDynamicSharedMemorySize, SM1);
    cudaFuncSetAttribute(k2, cudaFuncAttributeMaxDynamicSharedMemorySize, SM2);
    cudaFuncSetAttribute(k3, cudaFuncAttributeMaxDynamicSharedMemorySize, SM3);

    zero_stats_kernel<<<1, 128>>>();
    k1<<<B * (H / 32) * (W / 32), 256, SM1>>>(x, w1, h1);
    k2<<<B * 32 * 2, NT, SM2>>>(h1, w2, h2);
    k3<<<B * 32 * 2, NT, SM3>>>(h2, w3, out);
    bn_finalize_kernel<<<1, 64>>>(gamma, beta);
    bn_apply_kernel<<<(B * COUT * H * W / 4) / 256, 256>>>(out);
}